// round 13
// baseline (speedup 1.0000x reference)
#include <cuda_runtime.h>
#include <cuda_bf16.h>

// out[0,d,h,w,c] = in[0, z[d], row[h], col[w], 0]
// in (1,128,128,128,32) f32; z/row/col (64,) i32; out (1,64,64,64,32) f32.
//
// Two-phase split (keeps random DRAM gather reads out of the store kernel so
// the 32MB output stream stays L2-resident across graph replays — R7/R9
// measured DRAM<2% for the store phase):
//   A: 8MB random gathers -> 1MB compact buffer. 256 blocks, MLP=4/thread.
//   B: pure write stream. 1024 blocks, 8 independent (load,store) pairs/thread,
//      loads front-batched (all L2 hits on the 1MB compact buffer).

__device__ float g_compact[64 * 64 * 64];   // 1 MiB scratch

__global__ __launch_bounds__(256) void gather_kernel(
    const float* __restrict__ in,
    const int* __restrict__ zi,
    const int* __restrict__ ri,
    const int* __restrict__ ci)
{
    const int t = blockIdx.x * 256 + threadIdx.x;   // 0..65535
    #pragma unroll
    for (int k = 0; k < 4; k++) {
        const int pos = t + k * 65536;              // 4 independent positions
        const int w = pos & 63;
        const int h = (pos >> 6) & 63;
        const int d = pos >> 12;
        int src = (__ldg(zi + d) << 7) + __ldg(ri + h);   // z*128 + row
        src = ((src << 7) + __ldg(ci + w)) << 5;          // (*128 + col)*32
        g_compact[pos] = __ldg(in + src);
    }
}

__global__ __launch_bounds__(256) void broadcast_kernel(float4* __restrict__ out)
{
    const int t = blockIdx.x * 256 + threadIdx.x;   // 0..262143
    float v[8];
    #pragma unroll
    for (int k = 0; k < 8; k++)
        v[k] = __ldg(&g_compact[(t + k * 262144) >> 3]);   // L2 hits, batched
    #pragma unroll
    for (int k = 0; k < 8; k++)
        out[t + k * 262144] = make_float4(v[k], v[k], v[k], v[k]);
}

extern "C" void kernel_launch(void* const* d_in, const int* in_sizes, int n_in,
                              void* d_out, int out_size)
{
    const float* in  = (const float*)d_in[0];
    const int*   zi  = (const int*)d_in[1];
    const int*   ri  = (const int*)d_in[2];
    const int*   ci  = (const int*)d_in[3];
    float4*      out = (float4*)d_out;

    // A: 262144 positions / 4 per thread = 65536 threads = 256 blocks
    gather_kernel<<<256, 256>>>(in, zi, ri, ci);
    // B: 2097152 float4s / 8 per thread = 262144 threads = 1024 blocks
    broadcast_kernel<<<1024, 256>>>(out);
}